// round 5
// baseline (speedup 1.0000x reference)
#include <cuda_runtime.h>

// Problem constants (fixed by the reference)
#define SOUTN 8
#define P3N  8
#define P4N  4
#define NENT (P3N + P4N)   // 12 path entries total

constexpr int EPB     = 8;    // edges per batch (16 lanes per edge)
constexpr int THREADS = 128;
constexpr int SUPER   = 3;    // batches per super-iteration (amortizes constant reads)
constexpr int WST     = 208;  // per-edge W scratch stride; 208 mod 32 == 16 -> the warp's two
                              // groups read W on disjoint bank quads (conflict-free)
// per-edge W layout: [0,128) W3[p][i][k]; [128,192) W4[p][i][m]

__global__ __launch_bounds__(THREADS, 8)
void tp_kernel(const float* __restrict__ x0,
               const int*   __restrict__ i0,
               const float* __restrict__ x1,
               const float* __restrict__ C3,
               const float* __restrict__ C4,
               const int*   __restrict__ p3,
               const int*   __restrict__ p4,
               float* __restrict__ out,
               int E, int nSuper)
{
    // Transposed C3: sC3T[p*64 + (i*4+k)*4 + j] -> lane (i,k) reads its 4 j-values as one float4.
    __shared__ __align__(16) float sC3T[P3N * 64];
    // Transposed C4: sC4T[p*320 + (i*4+m)*20 + j*4 + k]; 20-word lane stride spreads bank quads.
    __shared__ __align__(16) float sC4T[P4N * 320];
    __shared__ int   sp3[P3N * 3];
    __shared__ int   sp4[P4N * 4];
    __shared__ int   sFlat[NENT];   // (wOffset<<16) | (s0<<8) | so, sorted by so
    __shared__ int   sMasks[2];     // [0]=flushMask, [1]=zeroMask
    __shared__ __align__(16) float sW[SUPER][EPB][WST];

    const int tid = threadIdx.x;

    // ---- stage constants (once per block), transposing for vector loads ----
    for (int idx = tid; idx < 512; idx += THREADS) {
        int p = idx >> 6, r = idx & 63;
        int i = r >> 4, j = (r >> 2) & 3, k = r & 3;
        sC3T[p * 64 + (i * 4 + k) * 4 + j] = C3[idx];
    }
    for (int idx = tid; idx < 1024; idx += THREADS) {
        int p = idx >> 8, r = idx & 255;
        int i = r >> 6, j = (r >> 4) & 3, k = (r >> 2) & 3, m = r & 3;
        sC4T[p * 320 + (i * 4 + m) * 20 + j * 4 + k] = C4[idx];
    }
    if (tid < P3N * 3) sp3[tid] = p3[tid];
    if (tid < P4N * 4) sp4[tid] = p4[tid];
    __syncthreads();

    // ---- build flat entry list sorted by output segment + flush/zero masks ----
    if (tid == 0) {
        int c = 0, fm = 0, zm = 0;
        for (int so = 0; so < SOUTN; so++) {
            const int start = c;
            for (int p = 0; p < P3N; p++)
                if (sp3[p * 3 + 2] == so)
                    sFlat[c++] = ((p * 16) << 16) | (sp3[p * 3 + 0] << 8) | so;
            for (int p = 0; p < P4N; p++)
                if (sp4[p * 4 + 3] == so)
                    sFlat[c++] = ((128 + p * 16) << 16) | (sp4[p * 4 + 0] << 8) | so;
            if (c > start) fm |= 1 << (c - 1);
            else           zm |= 1 << so;
        }
        sMasks[0] = fm; sMasks[1] = zm;
    }
    __syncthreads();

    // Cache block-constant entry metadata in registers.
    int ents[NENT];
    #pragma unroll
    for (int t = 0; t < NENT; t++) ents[t] = sFlat[t];
    const unsigned flushMask = (unsigned)sMasks[0];
    const unsigned zeroMask  = (unsigned)sMasks[1];

    const int g = tid >> 4;   // edge slot within batch (0..7)
    const int u = tid & 15;   // MUL index

    for (int sup = blockIdx.x; sup < nSuper; sup += gridDim.x) {
        const long long e0 = ((long long)sup * SUPER) * EPB + g;   // edge of sub-batch 0

        __syncwarp();   // previous super's main-phase reads of sW done before overwrite

        // gather indices early (latency hidden behind the build phase)
        int idxs[SUPER];
        #pragma unroll
        for (int s = 0; s < SUPER; s++) {
            const long long e = e0 + (long long)s * EPB;
            idxs[s] = (e < E) ? __ldg(i0 + e) : 0;
        }
        // prefetch first 4 gather vectors of sub-batch 0 (hidden behind build FMAs)
        const float* xr0 = x0 + (long long)idxs[0] * 512 + u * 4;
        float4 pv0 = __ldg(reinterpret_cast<const float4*>(xr0 + ((ents[0] >> 8) & 0xFF) * 64));
        float4 pv1 = __ldg(reinterpret_cast<const float4*>(xr0 + ((ents[1] >> 8) & 0xFF) * 64));
        float4 pv2 = __ldg(reinterpret_cast<const float4*>(xr0 + ((ents[2] >> 8) & 0xFF) * 64));
        float4 pv3 = __ldg(reinterpret_cast<const float4*>(xr0 + ((ents[3] >> 8) & 0xFF) * 64));

        // ---- W3 build: c loaded once per p, reused across SUPER sub-batches ----
        #pragma unroll
        for (int p = 0; p < P3N; p++) {
            const float4 c = *reinterpret_cast<const float4*>(sC3T + p * 64 + u * 4);
            const int seg = sp3[p * 3 + 1];
            #pragma unroll
            for (int s = 0; s < SUPER; s++) {
                const long long e = e0 + (long long)s * EPB;
                float w = 0.f;
                if (e < E) {
                    const float4 b = __ldg(reinterpret_cast<const float4*>(x1 + e * 32 + seg * 4));
                    w = b.x * c.x + b.y * c.y + b.z * c.z + b.w * c.w;
                }
                sW[s][g][p * 16 + u] = w;
            }
        }
        // ---- W4 build: q (16 floats) loaded once per p, reused across sub-batches ----
        #pragma unroll
        for (int p = 0; p < P4N; p++) {
            const float* q = sC4T + p * 320 + u * 20;
            const float4 q0 = *reinterpret_cast<const float4*>(q);
            const float4 q1 = *reinterpret_cast<const float4*>(q + 4);
            const float4 q2 = *reinterpret_cast<const float4*>(q + 8);
            const float4 q3 = *reinterpret_cast<const float4*>(q + 12);
            const int segB = sp4[p * 4 + 1];
            const int segC = sp4[p * 4 + 2];
            #pragma unroll
            for (int s = 0; s < SUPER; s++) {
                const long long e = e0 + (long long)s * EPB;
                float w = 0.f;
                if (e < E) {
                    const float4 b = __ldg(reinterpret_cast<const float4*>(x1 + e * 32 + segB * 4));
                    const float4 c = __ldg(reinterpret_cast<const float4*>(x1 + e * 32 + segC * 4));
                    w  = b.x * (c.x * q0.x + c.y * q0.y + c.z * q0.z + c.w * q0.w);
                    w += b.y * (c.x * q1.x + c.y * q1.y + c.z * q1.z + c.w * q1.w);
                    w += b.z * (c.x * q2.x + c.y * q2.y + c.z * q2.z + c.w * q2.w);
                    w += b.w * (c.x * q3.x + c.y * q3.y + c.z * q3.z + c.w * q3.w);
                }
                sW[s][g][128 + p * 16 + u] = w;
            }
        }
        __syncwarp();

        // ---- main contraction per sub-batch: flat 12-entry stream with flush stores ----
        #pragma unroll
        for (int s = 0; s < SUPER; s++) {
            const long long e = e0 + (long long)s * EPB;
            if (e < E) {
                const float* xr = x0 + (long long)idxs[s] * 512 + u * 4;
                const float* eg = sW[s][g];
                float* op = out + e * 512 + u * 4;
                float4 acc = make_float4(0.f, 0.f, 0.f, 0.f);
                #pragma unroll
                for (int t = 0; t < NENT; t++) {
                    const int ent = ents[t];
                    const int s0  = (ent >> 8) & 0xFF;
                    const int wo  = ent >> 16;
                    float4 v;
                    if      (s == 0 && t == 0) v = pv0;
                    else if (s == 0 && t == 1) v = pv1;
                    else if (s == 0 && t == 2) v = pv2;
                    else if (s == 0 && t == 3) v = pv3;
                    else v = __ldg(reinterpret_cast<const float4*>(xr + s0 * 64));
                    const float4 w0 = *reinterpret_cast<const float4*>(eg + wo);
                    const float4 w1 = *reinterpret_cast<const float4*>(eg + wo + 4);
                    const float4 w2 = *reinterpret_cast<const float4*>(eg + wo + 8);
                    const float4 w3 = *reinterpret_cast<const float4*>(eg + wo + 12);
                    acc.x += v.x*w0.x + v.y*w1.x + v.z*w2.x + v.w*w3.x;
                    acc.y += v.x*w0.y + v.y*w1.y + v.z*w2.y + v.w*w3.y;
                    acc.z += v.x*w0.z + v.y*w1.z + v.z*w2.z + v.w*w3.z;
                    acc.w += v.x*w0.w + v.y*w1.w + v.z*w2.w + v.w*w3.w;
                    if (flushMask & (1u << t)) {          // uniform across warp
                        __stcs(reinterpret_cast<float4*>(op + (ent & 0xFF) * 64), acc);
                        acc = make_float4(0.f, 0.f, 0.f, 0.f);
                    }
                }
                #pragma unroll
                for (int so = 0; so < SOUTN; so++)
                    if (zeroMask & (1u << so))
                        __stcs(reinterpret_cast<float4*>(op + so * 64),
                               make_float4(0.f, 0.f, 0.f, 0.f));
            }
        }
    }
}

extern "C" void kernel_launch(void* const* d_in, const int* in_sizes, int n_in,
                              void* d_out, int out_size)
{
    const float* x0 = (const float*)d_in[0];
    const int*   i0 = (const int*)  d_in[1];
    const float* x1 = (const float*)d_in[2];
    const float* C3 = (const float*)d_in[3];
    const float* C4 = (const float*)d_in[4];
    const int*   p3 = (const int*)  d_in[5];
    const int*   p4 = (const int*)  d_in[6];
    float* out = (float*)d_out;

    const int E = in_sizes[1];                           // i0 element count = number of edges
    const int nBatch = (E + EPB - 1) / EPB;
    const int nSuper = (nBatch + SUPER - 1) / SUPER;
    int grid = nSuper < 1184 ? nSuper : 1184;            // 8 blocks/SM resident, grid-stride
    tp_kernel<<<grid, THREADS>>>(x0, i0, x1, C3, C4, p3, p4, out, E, nSuper);
}